// round 2
// baseline (speedup 1.0000x reference)
#include <cuda_runtime.h>
#include <cstdint>

#define BB 16
#define NPTS 2048
#define MM 16
#define SS 128
#define NSPLIT 4
#define NCHUNK (NPTS / NSPLIT)        // 512
#define K1_THREADS 64
#define KPT (NCHUNK / K1_THREADS)     // 8 points per thread
#define NPAIR (KPT / 2)               // 4 f32x2 pairs
#define K2_SORT_BLOCKS ((BB * NPTS) / 256)   // 128
#define K2_CM_BLOCKS ((BB * MM) / 8)         // 32

static __device__ float g_d1[BB * NPTS * MM];              // [b][n][m] min-over-s
static __device__ float g_partmin[BB * MM * NSPLIT * SS];  // per (bm,chunk) per-s min-over-n-chunk
static __device__ float g_colmean[BB * MM];                // mean_s min_n (clamped)
static __device__ float g_part1[K2_SORT_BLOCKS];           // pcl_to_prim partials

// ---- packed f32x2 helpers (sm_10x; ptxas never auto-fuses these) ----
#define ADD2(d, a, b)    asm("add.rn.f32x2 %0, %1, %2;" : "=l"(d) : "l"(a), "l"(b))
#define MUL2(d, a, b)    asm("mul.rn.f32x2 %0, %1, %2;" : "=l"(d) : "l"(a), "l"(b))
#define FMA2(d, a, b, c) asm("fma.rn.f32x2 %0, %1, %2, %3;" : "=l"(d) : "l"(a), "l"(b), "l"(c))
#define PACK2(d, lo, hi) asm("mov.b64 %0, {%1, %2};" : "=l"(d) \
                             : "r"(__float_as_uint(lo)), "r"(__float_as_uint(hi)))
#define UNPACK2(lo, hi, s) do { unsigned _ul, _uh;                                  \
    asm("mov.b64 {%0, %1}, %2;" : "=r"(_ul), "=r"(_uh) : "l"(s));                   \
    (lo) = __uint_as_float(_ul); (hi) = __uint_as_float(_uh); } while (0)

// ---------------------------------------------------------------------------
// Kernel 1: one CTA per (b, m, n-chunk). Exact diff-form distances in packed
// f32x2 (3 fma-pipe instrs / element). Per-thread min-over-s in registers;
// per-s min-over-chunk via REDUX + smem atomicMin, written to g_partmin.
// Distances are exact sums of squares -> always >= 0 -> uint-min trick valid
// with no clamps, and no cancellation error.
// ---------------------------------------------------------------------------
__global__ __launch_bounds__(K1_THREADS) void k1(const float* __restrict__ pcl,
                                                 const float* __restrict__ prim) {
    const int bid = blockIdx.x;            // = bm * NSPLIT + chunk
    const int chunk = bid & (NSPLIT - 1);
    const int bm = bid >> 2;
    const int b = bm >> 4;
    const int m = bm & 15;
    const int tid = threadIdx.x;

    __shared__ float4 spA[SS];   // (a,a,c,c) duplicated for packed broadcast
    __shared__ float2 spB[SS];   // (d,d)
    __shared__ unsigned smin[SS];

    const float* pp = prim + (size_t)(b * MM + m) * SS * 3;
    for (int s = tid; s < SS; s += K1_THREADS) {
        float a = pp[3 * s + 0];
        float c = pp[3 * s + 1];
        float d = pp[3 * s + 2];
        spA[s] = make_float4(a, a, c, c);
        spB[s] = make_float2(d, d);
        smin[s] = 0x7f7fffffu;  // FLT_MAX bits
    }
    __syncthreads();

    // Load this thread's 8 pcl points (negated), packed into 4 f32x2 pairs.
    unsigned long long nx2[NPAIR], ny2[NPAIR], nz2[NPAIR];
    float dmin[KPT];
#pragma unroll
    for (int p = 0; p < NPAIR; p++) {
        int n0 = chunk * NCHUNK + (2 * p) * K1_THREADS + tid;
        int n1 = n0 + K1_THREADS;
        const float* x0 = pcl + ((size_t)(b * NPTS + n0) * MM + m) * 3;
        const float* x1 = pcl + ((size_t)(b * NPTS + n1) * MM + m) * 3;
        PACK2(nx2[p], -x0[0], -x1[0]);
        PACK2(ny2[p], -x0[1], -x1[1]);
        PACK2(nz2[p], -x0[2], -x1[2]);
        dmin[2 * p] = 3.4e38f;
        dmin[2 * p + 1] = 3.4e38f;
    }

#pragma unroll 2
    for (int s = 0; s < SS; s++) {
        float4 va = spA[s];
        float2 vb = spB[s];
        unsigned long long aa, cc, dd;
        PACK2(aa, va.x, va.y);
        PACK2(cc, va.z, va.w);
        PACK2(dd, vb.x, vb.y);
        float m8 = 3.4e38f;
#pragma unroll
        for (int p = 0; p < NPAIR; p++) {
            unsigned long long dx, dy, dz, t;
            ADD2(dx, aa, nx2[p]);          // a - x
            ADD2(dy, cc, ny2[p]);
            ADD2(dz, dd, nz2[p]);
            MUL2(t, dz, dz);
            FMA2(t, dy, dy, t);
            FMA2(t, dx, dx, t);            // exact ||p - x||^2 >= 0
            float f0, f1;
            UNPACK2(f0, f1, t);
            dmin[2 * p]     = fminf(dmin[2 * p], f0);
            dmin[2 * p + 1] = fminf(dmin[2 * p + 1], f1);
            m8 = fminf(m8, fminf(f0, f1));
        }
        unsigned u = __reduce_min_sync(0xffffffffu, __float_as_uint(m8));
        if ((tid & 31) == 0) atomicMin(&smin[s], u);
    }

    // Write d1 (min over s) for this thread's 8 points.
#pragma unroll
    for (int j = 0; j < KPT; j++) {
        int n = chunk * NCHUNK + j * K1_THREADS + tid;
        g_d1[(size_t)(b * NPTS + n) * MM + m] = dmin[j];
    }
    __syncthreads();

    // Per-CTA partial per-s min-over-n-chunk.
    for (int s = tid; s < SS; s += K1_THREADS)
        g_partmin[(size_t)bid * SS + s] = __uint_as_float(smin[s]);
}

// ---------------------------------------------------------------------------
// Kernel 2:
//  blocks [0, 128): per (b,n) Batcher odd-even merge sort (63 comparators) of
//  the M=16 (dist, prob) pairs, stick-breaking sum, block-tree partial.
//  blocks [128, 160): colmean — combine the 4 chunk-partial per-s mins, clamp,
//  mean over s, one warp per (b,m).
// ---------------------------------------------------------------------------
__global__ __launch_bounds__(256) void k2(const float* __restrict__ probs) {
    if (blockIdx.x < K2_SORT_BLOCKS) {
        const int idx = blockIdx.x * 256 + threadIdx.x;  // < B*N
        const int b = idx / NPTS;

        float d[MM], p[MM];
        const float4* dp = (const float4*)(g_d1 + (size_t)idx * MM);
#pragma unroll
        for (int i = 0; i < 4; i++) {
            float4 v = dp[i];
            d[4 * i + 0] = v.x; d[4 * i + 1] = v.y;
            d[4 * i + 2] = v.z; d[4 * i + 3] = v.w;
        }
#pragma unroll
        for (int i = 0; i < MM; i++) p[i] = probs[b * MM + i];

        // Batcher merge-exchange sort network, n=16 (63 comparators),
        // ascending by d. All indices compile-time -> registers.
#pragma unroll
        for (int pw = 8; pw >= 1; pw >>= 1) {
#pragma unroll
            for (int q = 8; q >= pw; q >>= 1) {
                const int dd = (q == 8) ? pw : 2 * q - pw;
                const int r  = (q == 8) ? 0 : pw;
#pragma unroll
                for (int i = 0; i + dd < MM; i++) {
                    if ((i & pw) == r) {
                        if (d[i] > d[i + dd]) {
                            float t = d[i]; d[i] = d[i + dd]; d[i + dd] = t;
                            float u = p[i]; p[i] = p[i + dd]; p[i + dd] = u;
                        }
                    }
                }
            }
        }

        // sum_k d_(k) * p_(k) * prod_{j<k} (1 - p_(j))
        float run = 1.0f, sum = 0.0f;
#pragma unroll
        for (int i = 0; i < MM; i++) {
            sum += d[i] * p[i] * run;
            run *= (1.0f - p[i]);
        }

        __shared__ float red[256];
        red[threadIdx.x] = sum;
        __syncthreads();
        for (int off = 128; off > 0; off >>= 1) {
            if (threadIdx.x < off) red[threadIdx.x] += red[threadIdx.x + off];
            __syncthreads();
        }
        if (threadIdx.x == 0) g_part1[blockIdx.x] = red[0];
    } else {
        // colmean blocks: 8 warps per block, one (b,m) per warp.
        const int bb = blockIdx.x - K2_SORT_BLOCKS;     // 0..31
        const int w = threadIdx.x >> 5;
        const int lane = threadIdx.x & 31;
        const int bm = bb * 8 + w;

        const float* pm = g_partmin + (size_t)bm * NSPLIT * SS;
        float sum = 0.0f;
#pragma unroll
        for (int i = 0; i < SS / 32; i++) {
            int s = lane + 32 * i;
            float mn = fminf(fminf(pm[0 * SS + s], pm[1 * SS + s]),
                             fminf(pm[2 * SS + s], pm[3 * SS + s]));
            if (mn >= 1e30f) mn = 0.0f;   // INF_CLAMP rule
            sum += mn;
        }
#pragma unroll
        for (int off = 16; off > 0; off >>= 1)
            sum += __shfl_down_sync(0xffffffffu, sum, off);
        if (lane == 0) g_colmean[bm] = sum * (1.0f / SS);
    }
}

// ---------------------------------------------------------------------------
// Kernel 3: single block. Superquadric areas + per-b normalization, combine
// everything, write the 4 output scalars.
// ---------------------------------------------------------------------------
__global__ __launch_bounds__(256) void k3(const float* __restrict__ size_,
                                          const float* __restrict__ probs,
                                          float* __restrict__ out, int out_size) {
    const int tid = threadIdx.x;  // 256 == B*M
    const float FOUR_PI = 12.566370614359172f;

    __shared__ float area[256];
    __shared__ float red[256];
    __shared__ float p1_shared;

    const int b = tid >> 4;

    float s0 = size_[tid * 3 + 0];
    float s1 = size_[tid * 3 + 1];
    float s2 = size_[tid * 3 + 2];
    float inner = (powf(s0 * s1, 1.6f) + powf(s0 * s2, 1.6f) + powf(s1 * s2, 1.6f)) * (1.0f / 3.0f);
    float ar = FOUR_PI * powf(inner, 0.625f);
    area[tid] = ar;
    __syncthreads();

    float sb = 0.0f;
#pragma unroll
    for (int j = 0; j < MM; j++) sb += area[b * MM + j];

    float contrib = g_colmean[tid] * probs[tid] * ((float)MM * ar / sb) * (1.0f / (BB * MM));

    red[tid] = (tid < K2_SORT_BLOCKS) ? g_part1[tid] : 0.0f;
    __syncthreads();
    for (int off = 128; off > 0; off >>= 1) {
        if (tid < off) red[tid] += red[tid + off];
        __syncthreads();
    }
    if (tid == 0) p1_shared = red[0];
    __syncthreads();

    red[tid] = contrib;
    __syncthreads();
    for (int off = 128; off > 0; off >>= 1) {
        if (tid < off) red[tid] += red[tid + off];
        __syncthreads();
    }

    if (tid == 0) {
        float pcl_to_prim = p1_shared * (1.0f / ((float)BB * (float)NPTS));
        float prim_to_pcl = red[0];
        float total = pcl_to_prim + prim_to_pcl;
        if (out_size > 0) out[0] = total;
        if (out_size > 1) out[1] = pcl_to_prim;
        if (out_size > 2) out[2] = prim_to_pcl;
        if (out_size > 3) out[3] = 0.0f;
    }
}

extern "C" void kernel_launch(void* const* d_in, const int* in_sizes, int n_in,
                              void* d_out, int out_size) {
    const float* pcl   = (const float*)d_in[0];  // (B, N, M, 3)
    const float* prim  = (const float*)d_in[1];  // (B, M, S, 3)
    const float* size_ = (const float*)d_in[2];  // (B, M, 3)
    const float* probs = (const float*)d_in[3];  // (B, M)

    k1<<<BB * MM * NSPLIT, K1_THREADS>>>(pcl, prim);
    k2<<<K2_SORT_BLOCKS + K2_CM_BLOCKS, 256>>>(probs);
    k3<<<1, 256>>>(size_, probs, (float*)d_out, out_size);
}

// round 3
// speedup vs baseline: 1.2665x; 1.2665x over previous
#include <cuda_runtime.h>
#include <cstdint>

#define BB 16
#define NPTS 2048
#define MM 16
#define SS 128
#define NSPLIT 4
#define NCHUNK (NPTS / NSPLIT)        // 512 n per CTA
#define TX 64                          // threads in n direction
#define TY 4                           // threads in s direction
#define NCNT (NCHUNK / TX)             // 8 n per thread
#define NPAIR (NCNT / 2)               // 4 packed pairs
#define SCNT (SS / TY)                 // 32 s per thread
#define K2_SORT_BLOCKS ((BB * NPTS) / 256)   // 128
#define K2_CM_BLOCKS ((BB * MM) / 8)         // 32

static __device__ float g_d1[BB * NPTS * MM];              // [b][n][m] min-over-s
static __device__ float g_partmin[BB * MM * NSPLIT * SS];  // per (bm,chunk), per-s min-over-chunk
static __device__ float g_colmean[BB * MM];                // mean_s min_n (clamped)
static __device__ float g_part1[K2_SORT_BLOCKS];           // pcl_to_prim partials

// ---- packed f32x2 helpers ----
#define ADD2(d, a, b)    asm("add.rn.f32x2 %0, %1, %2;" : "=l"(d) : "l"(a), "l"(b))
#define FMA2(d, a, b, c) asm("fma.rn.f32x2 %0, %1, %2, %3;" : "=l"(d) : "l"(a), "l"(b), "l"(c))
#define PACK2(d, lo, hi) asm("mov.b64 %0, {%1, %2};" : "=l"(d) \
                             : "r"(__float_as_uint(lo)), "r"(__float_as_uint(hi)))
#define UNPACK2(lo, hi, s) do { unsigned _ul, _uh;                                  \
    asm("mov.b64 {%0, %1}, %2;" : "=r"(_ul), "=r"(_uh) : "l"(s));                   \
    (lo) = __uint_as_float(_ul); (hi) = __uint_as_float(_uh); } while (0)

// ---------------------------------------------------------------------------
// Kernel 1: one CTA per (b, m, n-chunk). 2D register tiling: thread (x,y)
// owns n = {j*64+x : j<8} and s = {y*32+k : k<32}. Hot loop is pure
// register math: dist = (|p|^2 + |x|^2) - 2 p.x via packed f32x2
// (4 fma-pipe instrs / pair) + 4 scalar FMNMX per pair. No shuffles, no
// atomics, no syncs until the one-time epilogue reduction.
// ---------------------------------------------------------------------------
__global__ __launch_bounds__(TX * TY) void k1(const float* __restrict__ pcl,
                                              const float* __restrict__ prim) {
    const int bid = blockIdx.x;            // = bm * NSPLIT + chunk
    const int chunk = bid & (NSPLIT - 1);
    const int bm = bid >> 2;
    const int b = bm >> 4;
    const int m = bm & 15;
    const int tid = threadIdx.x;
    const int x = tid & (TX - 1);
    const int y = tid >> 6;                // 0..3
    const int lane = tid & 31;
    const int warp = tid >> 5;             // = 2*y + (x>=32)

    // smem: pre-packed broadcast-ready 64-bit lanes per s:
    //   sAC[s] = {aa, cc}, sDQ[s] = {dd, qq}  (a,c,d = prim coords, q = |p|^2)
    __shared__ ulonglong2 sAC[SS];
    __shared__ ulonglong2 sDQ[SS];
    __shared__ float sred[TY * NCHUNK];    // 4 x 512 floats = 8KB (dmin combine)
    __shared__ float sbuf[8][32];          // per-warp smin results

    const float* pp = prim + (size_t)(b * MM + m) * SS * 3;
    for (int s = tid; s < SS; s += TX * TY) {
        float a = pp[3 * s + 0];
        float c = pp[3 * s + 1];
        float d = pp[3 * s + 2];
        float q = a * a + c * c + d * d;
        unsigned long long aa, cc, dd, qq;
        PACK2(aa, a, a); PACK2(cc, c, c); PACK2(dd, d, d); PACK2(qq, q, q);
        sAC[s] = make_ulonglong2(aa, cc);
        sDQ[s] = make_ulonglong2(dd, qq);
    }
    __syncthreads();

    // Load this thread's 8 pcl points: nx=-2px etc, uu=|x|^2, packed in pairs
    // (pair p covers n_local = (2p)*64+x and (2p+1)*64+x).
    unsigned long long nx2[NPAIR], ny2[NPAIR], nz2[NPAIR], uu2[NPAIR];
    float dmin[NCNT];
#pragma unroll
    for (int p = 0; p < NPAIR; p++) {
        int n0 = chunk * NCHUNK + (2 * p) * TX + x;
        int n1 = n0 + TX;
        const float* x0 = pcl + ((size_t)(b * NPTS + n0) * MM + m) * 3;
        const float* x1 = pcl + ((size_t)(b * NPTS + n1) * MM + m) * 3;
        float a0 = x0[0], b0 = x0[1], c0 = x0[2];
        float a1 = x1[0], b1 = x1[1], c1 = x1[2];
        PACK2(nx2[p], -2.0f * a0, -2.0f * a1);
        PACK2(ny2[p], -2.0f * b0, -2.0f * b1);
        PACK2(nz2[p], -2.0f * c0, -2.0f * c1);
        PACK2(uu2[p], a0 * a0 + b0 * b0 + c0 * c0, a1 * a1 + b1 * b1 + c1 * c1);
        dmin[2 * p] = 3.4e38f;
        dmin[2 * p + 1] = 3.4e38f;
    }

    float smin[SCNT];
#pragma unroll
    for (int k = 0; k < SCNT; k++) smin[k] = 3.4e38f;

    // ---- hot loop: 32 s x 8 n per thread, all in registers ----
#pragma unroll
    for (int k = 0; k < SCNT; k++) {
        const int s = y * SCNT + k;
        ulonglong2 ac = sAC[s];
        ulonglong2 dq = sDQ[s];
        float sm0 = 3.4e38f, sm1 = 3.4e38f;   // 2 partial chains (depth 4)
#pragma unroll
        for (int p = 0; p < NPAIR; p++) {
            unsigned long long t;
            ADD2(t, dq.y, uu2[p]);             // q + |x|^2
            FMA2(t, ac.x, nx2[p], t);          // -2 a x
            FMA2(t, ac.y, ny2[p], t);
            FMA2(t, dq.x, nz2[p], t);
            float f0, f1;
            UNPACK2(f0, f1, t);
            dmin[2 * p]     = fminf(dmin[2 * p], f0);
            dmin[2 * p + 1] = fminf(dmin[2 * p + 1], f1);
            sm0 = fminf(sm0, f0);
            sm1 = fminf(sm1, f1);
        }
        smin[k] = fminf(sm0, sm1);
    }

    // ---- epilogue 1: smin — warp butterfly (lanes of a warp share y => same s set) ----
#pragma unroll
    for (int k = 0; k < SCNT; k++) {
#pragma unroll
        for (int off = 16; off > 0; off >>= 1)
            smin[k] = fminf(smin[k], __shfl_xor_sync(0xffffffffu, smin[k], off));
    }
    if (lane == 0) {
#pragma unroll
        for (int k = 0; k < SCNT; k++) sbuf[warp][k] = smin[k];
    }

    // ---- epilogue 2: dmin — combine the 4 y-slices via smem ----
#pragma unroll
    for (int j = 0; j < NCNT; j++) sred[y * NCHUNK + j * TX + x] = dmin[j];
    __syncthreads();

    // 512 n / 256 threads = 2 n per thread
#pragma unroll
    for (int r = 0; r < 2; r++) {
        int nl = r * 256 + tid;
        float v = fminf(fminf(sred[0 * NCHUNK + nl], sred[1 * NCHUNK + nl]),
                        fminf(sred[2 * NCHUNK + nl], sred[3 * NCHUNK + nl]));
        int n = chunk * NCHUNK + nl;
        g_d1[(size_t)(b * NPTS + n) * MM + m] = v;
    }

    // per-s partial min over this chunk: combine warp pairs (2y, 2y+1)
    if (tid < SS) {
        int yy = tid >> 5, kk = tid & 31;
        g_partmin[(size_t)bid * SS + tid] = fminf(sbuf[2 * yy][kk], sbuf[2 * yy + 1][kk]);
    }
}

// ---------------------------------------------------------------------------
// Kernel 2:
//  blocks [0,128): per (b,n) odd-even transposition sort of M=16 (dist,prob),
//  stick-breaking sum, block-tree partial.  (R1-proven version.)
//  blocks [128,160): colmean — combine 4 chunk mins, clamp, mean over s.
// ---------------------------------------------------------------------------
__global__ __launch_bounds__(256) void k2(const float* __restrict__ probs) {
    if (blockIdx.x < K2_SORT_BLOCKS) {
        const int idx = blockIdx.x * 256 + threadIdx.x;  // < B*N
        const int b = idx / NPTS;

        float d[MM], p[MM];
        const float4* dp = (const float4*)(g_d1 + (size_t)idx * MM);
#pragma unroll
        for (int i = 0; i < 4; i++) {
            float4 v = dp[i];
            d[4 * i + 0] = v.x; d[4 * i + 1] = v.y;
            d[4 * i + 2] = v.z; d[4 * i + 3] = v.w;
        }
#pragma unroll
        for (int i = 0; i < MM; i++) p[i] = probs[b * MM + i];

#pragma unroll
        for (int r = 0; r < MM; r++) {
#pragma unroll
            for (int i = (r & 1); i + 1 < MM; i += 2) {
                if (d[i] > d[i + 1]) {
                    float td = d[i]; d[i] = d[i + 1]; d[i + 1] = td;
                    float tp = p[i]; p[i] = p[i + 1]; p[i + 1] = tp;
                }
            }
        }

        float run = 1.0f, sum = 0.0f;
#pragma unroll
        for (int i = 0; i < MM; i++) {
            sum += d[i] * p[i] * run;
            run *= (1.0f - p[i]);
        }

        __shared__ float red[256];
        red[threadIdx.x] = sum;
        __syncthreads();
        for (int off = 128; off > 0; off >>= 1) {
            if (threadIdx.x < off) red[threadIdx.x] += red[threadIdx.x + off];
            __syncthreads();
        }
        if (threadIdx.x == 0) g_part1[blockIdx.x] = red[0];
    } else {
        const int bb = blockIdx.x - K2_SORT_BLOCKS;     // 0..31
        const int w = threadIdx.x >> 5;
        const int lane = threadIdx.x & 31;
        const int bm = bb * 8 + w;

        const float* pm = g_partmin + (size_t)bm * NSPLIT * SS;
        float sum = 0.0f;
#pragma unroll
        for (int i = 0; i < SS / 32; i++) {
            int s = lane + 32 * i;
            float mn = fminf(fminf(pm[0 * SS + s], pm[1 * SS + s]),
                             fminf(pm[2 * SS + s], pm[3 * SS + s]));
            if (mn >= 1e30f) mn = 0.0f;   // INF_CLAMP rule
            sum += mn;
        }
#pragma unroll
        for (int off = 16; off > 0; off >>= 1)
            sum += __shfl_down_sync(0xffffffffu, sum, off);
        if (lane == 0) g_colmean[bm] = sum * (1.0f / SS);
    }
}

// ---------------------------------------------------------------------------
// Kernel 3: single block. Areas + normalization + final combine.
// ---------------------------------------------------------------------------
__global__ __launch_bounds__(256) void k3(const float* __restrict__ size_,
                                          const float* __restrict__ probs,
                                          float* __restrict__ out, int out_size) {
    const int tid = threadIdx.x;  // 256 == B*M
    const float FOUR_PI = 12.566370614359172f;

    __shared__ float area[256];
    __shared__ float red[256];
    __shared__ float p1_shared;

    const int b = tid >> 4;

    float s0 = size_[tid * 3 + 0];
    float s1 = size_[tid * 3 + 1];
    float s2 = size_[tid * 3 + 2];
    float inner = (powf(s0 * s1, 1.6f) + powf(s0 * s2, 1.6f) + powf(s1 * s2, 1.6f)) * (1.0f / 3.0f);
    float ar = FOUR_PI * powf(inner, 0.625f);
    area[tid] = ar;
    __syncthreads();

    float sb = 0.0f;
#pragma unroll
    for (int j = 0; j < MM; j++) sb += area[b * MM + j];

    float contrib = g_colmean[tid] * probs[tid] * ((float)MM * ar / sb) * (1.0f / (BB * MM));

    red[tid] = (tid < K2_SORT_BLOCKS) ? g_part1[tid] : 0.0f;
    __syncthreads();
    for (int off = 128; off > 0; off >>= 1) {
        if (tid < off) red[tid] += red[tid + off];
        __syncthreads();
    }
    if (tid == 0) p1_shared = red[0];
    __syncthreads();

    red[tid] = contrib;
    __syncthreads();
    for (int off = 128; off > 0; off >>= 1) {
        if (tid < off) red[tid] += red[tid + off];
        __syncthreads();
    }

    if (tid == 0) {
        float pcl_to_prim = p1_shared * (1.0f / ((float)BB * (float)NPTS));
        float prim_to_pcl = red[0];
        float total = pcl_to_prim + prim_to_pcl;
        if (out_size > 0) out[0] = total;
        if (out_size > 1) out[1] = pcl_to_prim;
        if (out_size > 2) out[2] = prim_to_pcl;
        if (out_size > 3) out[3] = 0.0f;
    }
}

extern "C" void kernel_launch(void* const* d_in, const int* in_sizes, int n_in,
                              void* d_out, int out_size) {
    const float* pcl   = (const float*)d_in[0];  // (B, N, M, 3)
    const float* prim  = (const float*)d_in[1];  // (B, M, S, 3)
    const float* size_ = (const float*)d_in[2];  // (B, M, 3)
    const float* probs = (const float*)d_in[3];  // (B, M)

    k1<<<BB * MM * NSPLIT, TX * TY>>>(pcl, prim);
    k2<<<K2_SORT_BLOCKS + K2_CM_BLOCKS, 256>>>(probs);
    k3<<<1, 256>>>(size_, probs, (float*)d_out, out_size);
}